// round 1
// baseline (speedup 1.0000x reference)
#include <cuda_runtime.h>
#include <cuda_bf16.h>
#include <math.h>

// Problem constants (fixed shapes)
#define NN 200000
#define DD 256
#define HH 128      // D/2
#define BB 1024
#define OUT 256

// ---------------- scratch (device globals, no allocation) ----------------
__device__ int   g_segstart[BB + 1];
__device__ float g_s[NN];                 // per-node attention score
__device__ float g_typesums[BB * 768];    // [B][3][256]
__device__ float g_combined[BB * 768];    // [mean | attn | phys]
__device__ float g_H[BB * 512];           // hidden of final MLP
__device__ float g_wcat[768 * 256];       // [we; wv; wp]

// ---------------- f32x2 helpers ----------------
__device__ __forceinline__ unsigned long long ffma2(unsigned long long a,
                                                    unsigned long long b,
                                                    unsigned long long c) {
    unsigned long long d;
    asm("fma.rn.f32x2 %0, %1, %2, %3;" : "=l"(d) : "l"(a), "l"(b), "l"(c));
    return d;
}
__device__ __forceinline__ unsigned long long pack2(float lo, float hi) {
    unsigned long long r;
    asm("mov.b64 %0, {%1, %2};" : "=l"(r) : "f"(lo), "f"(hi));
    return r;
}
__device__ __forceinline__ void unpack2(unsigned long long v, float& lo, float& hi) {
    asm("mov.b64 {%0, %1}, %2;" : "=f"(lo), "=f"(hi) : "l"(v));
}

// ---------------- K0: segment boundaries (batch is sorted, all segs nonempty)
__global__ void k0_bounds(const int* __restrict__ batch) {
    int i = blockIdx.x * 256 + threadIdx.x;
    if (i < NN) {
        if (i == 0 || batch[i] != batch[i - 1]) g_segstart[batch[i]] = i;
    }
    if (i == 0) g_segstart[BB] = NN;
}

// ---------------- K1: per-node scores  s = tanh(x@aw1 + ab1) @ aw2 + ab2
// Block: 256 threads = 8 j-groups (16 hidden each) x 32 node-groups (4 nodes each)
// -> 128 nodes/block, all 128 hidden in one x pass. f32x2 dual-rate FMAs.
__global__ __launch_bounds__(256, 2)
void k1_scores(const float* __restrict__ x,
               const float* __restrict__ aw1,
               const float* __restrict__ ab1,
               const float* __restrict__ aw2,
               const float* __restrict__ ab2) {
    __shared__ float  xs[32][128];              // 16 KB : x chunk transposed [k][node]
    __shared__ float2 ws[32][128];              // 32 KB : aw1 chunk duplicated pairs

    const int tid = threadIdx.x;
    const int jg = tid >> 5;                    // 0..7 (warp-uniform)
    const int ng = tid & 31;                    // node group
    const int jbase = jg * 16;
    const int nodebase = blockIdx.x * 128;

    unsigned long long acc[2][16];
#pragma unroll
    for (int jj = 0; jj < 16; jj++) {
        float b = ab1[jbase + jj];
        unsigned long long p = pack2(b, b);
        acc[0][jj] = p; acc[1][jj] = p;
    }

    for (int kb = 0; kb < DD; kb += 32) {
        __syncthreads();
        // load x chunk (transposed into smem)
#pragma unroll
        for (int r = 0; r < 4; r++) {
            int flat = tid + 256 * r;           // 0..1023
            int n = flat >> 3;                  // 0..127
            int q = flat & 7;                   // float4 idx within 32 k
            float4 v = make_float4(0.f, 0.f, 0.f, 0.f);
            int node = nodebase + n;
            if (node < NN)
                v = *(const float4*)(x + (size_t)node * DD + kb + 4 * q);
            xs[4 * q + 0][n] = v.x; xs[4 * q + 1][n] = v.y;
            xs[4 * q + 2][n] = v.z; xs[4 * q + 3][n] = v.w;
        }
        // load aw1 chunk, duplicate each weight into both f32x2 lanes
#pragma unroll
        for (int r = 0; r < 16; r++) {
            int flat = tid + 256 * r;           // 0..4095
            int kk = flat >> 7;
            int j  = flat & 127;
            float w = aw1[(kb + kk) * HH + j];
            ws[kk][j] = make_float2(w, w);
        }
        __syncthreads();

#pragma unroll 4
        for (int kk = 0; kk < 32; kk++) {
            unsigned long long x0 = *(const unsigned long long*)&xs[kk][4 * ng];
            unsigned long long x1 = *(const unsigned long long*)&xs[kk][4 * ng + 2];
#pragma unroll
            for (int jj = 0; jj < 16; jj++) {
                unsigned long long w = *(const unsigned long long*)&ws[kk][jbase + jj];
                acc[0][jj] = ffma2(x0, w, acc[0][jj]);
                acc[1][jj] = ffma2(x1, w, acc[1][jj]);
            }
        }
    }

    // epilogue: partial score per node over this thread's 16 hidden units
    float part[4] = {0.f, 0.f, 0.f, 0.f};
#pragma unroll
    for (int p = 0; p < 2; p++) {
#pragma unroll
        for (int jj = 0; jj < 16; jj++) {
            float lo, hi;
            unpack2(acc[p][jj], lo, hi);
            float w2v = aw2[jbase + jj];
            part[2 * p + 0] += tanhf(lo) * w2v;
            part[2 * p + 1] += tanhf(hi) * w2v;
        }
    }

    __syncthreads();
    float* red = &xs[0][0];                     // reuse 16 KB: [8 groups][128 nodes]
#pragma unroll
    for (int q = 0; q < 4; q++) red[jg * 128 + 4 * ng + q] = part[q];
    __syncthreads();

    if (tid < 128) {
        float sv = ab2[0];
#pragma unroll
        for (int g = 0; g < 8; g++) sv += red[g * 128 + tid];
        int node = nodebase + tid;
        if (node < NN) g_s[node] = sv;
    }
}

// ---------------- K2: per-segment softmax stats + all pools (one x pass)
__global__ __launch_bounds__(128)
void k2_pool(const float* __restrict__ x,
             const int* __restrict__ ntm,       // [N][3] one-hot int
             const float* __restrict__ be,
             const float* __restrict__ bv,
             const float* __restrict__ bp) {
    const int b = blockIdx.x;
    const int tid = threadIdx.x;
    const int st = g_segstart[b];
    const int en = g_segstart[b + 1];

    __shared__ float red[128];

    // segment max of s
    float m = -1e30f;
    for (int i = st + tid; i < en; i += 128) m = fmaxf(m, g_s[i]);
    red[tid] = m; __syncthreads();
    for (int off = 64; off > 0; off >>= 1) {
        if (tid < off) red[tid] = fmaxf(red[tid], red[tid + off]);
        __syncthreads();
    }
    m = red[0]; __syncthreads();

    // segment sum of exp(s-m)
    float z = 0.f;
    for (int i = st + tid; i < en; i += 128) z += expf(g_s[i] - m);
    red[tid] = z; __syncthreads();
    for (int off = 64; off > 0; off >>= 1) {
        if (tid < off) red[tid] += red[tid + off];
        __syncthreads();
    }
    z = red[0]; __syncthreads();
    float inv_z = 1.f / z;

    // single pass over x: mean sum, attn pool, per-type sums, type counts
    const int d0 = tid * 2;
    float am0 = 0.f, am1 = 0.f, aa0 = 0.f, aa1 = 0.f;
    float t00 = 0.f, t01 = 0.f, t10 = 0.f, t11 = 0.f, t20 = 0.f, t21 = 0.f;
    int c0 = 0, c1 = 0, c2 = 0;

    for (int i = st; i < en; i++) {
        float w = expf(g_s[i] - m) * inv_z;
        int t = ntm[i * 3 + 1] + 2 * ntm[i * 3 + 2];
        float2 xv = *(const float2*)(x + (size_t)i * DD + d0);
        am0 += xv.x; am1 += xv.y;
        aa0 += w * xv.x; aa1 += w * xv.y;
        if (t == 0)      { t00 += xv.x; t01 += xv.y; c0++; }
        else if (t == 1) { t10 += xv.x; t11 += xv.y; c1++; }
        else             { t20 += xv.x; t21 += xv.y; c2++; }
    }

    float invc = 1.f / (float)(en - st);
    float* comb = g_combined + (size_t)b * 768;
    comb[d0]       = am0 * invc;  comb[d0 + 1]       = am1 * invc;
    comb[256 + d0] = aa0;         comb[256 + d0 + 1] = aa1;

    float* ts = g_typesums + (size_t)b * 768;
    ts[d0]           = t00; ts[d0 + 1]           = t01;
    ts[256 + d0]     = t10; ts[256 + d0 + 1]     = t11;
    ts[512 + d0]     = t20; ts[512 + d0 + 1]     = t21;

    // phys bias: count_t * b_t  (GEMM will accumulate on top)
    float f0 = (float)c0, f1 = (float)c1, f2 = (float)c2;
    comb[512 + d0]     = f0 * be[d0]     + f1 * bv[d0]     + f2 * bp[d0];
    comb[512 + d0 + 1] = f0 * be[d0 + 1] + f1 * bv[d0 + 1] + f2 * bp[d0 + 1];
}

// ---------------- weight concat [we; wv; wp] -> g_wcat[768][256]
__global__ void k_cat(const float* __restrict__ we,
                      const float* __restrict__ wv,
                      const float* __restrict__ wp) {
    int t = blockIdx.x * 256 + threadIdx.x;
    if (t < 768 * 256) {
        int k = t >> 8;
        int n = t & 255;
        float v;
        if (k < 256)      v = we[k * 256 + n];
        else if (k < 512) v = wv[(k - 256) * 256 + n];
        else              v = wp[(k - 512) * 256 + n];
        g_wcat[t] = v;
    }
}

// ---------------- generic tiled GEMM: C = act(A[M][K] @ W[K][N] + bias)
// ACT: 0 = accumulate into C (C += A@W), 1 = silu(.+bias), 2 = .+bias
template <int ACT>
__global__ __launch_bounds__(256)
void gemm_k(const float* __restrict__ A, int lda,
            const float* __restrict__ W, int ldw,
            float* __restrict__ C, int ldc, int coff,
            const float* __restrict__ bias, int Kdim) {
    __shared__ float As[32][64];
    __shared__ float Ws[32][64];

    const int tid = threadIdx.x;
    const int tx = tid & 15;
    const int ty = tid >> 4;
    const int colb = blockIdx.x * 64;
    const int rowb = blockIdx.y * 64;

    float acc[4][4];
#pragma unroll
    for (int i = 0; i < 4; i++)
#pragma unroll
        for (int j = 0; j < 4; j++) acc[i][j] = 0.f;

    for (int kb = 0; kb < Kdim; kb += 32) {
        __syncthreads();
#pragma unroll
        for (int r = 0; r < 2; r++) {
            int flat = tid + 256 * r;           // 0..511
            int row = flat >> 3;
            int q = flat & 7;
            float4 v = *(const float4*)(A + (size_t)(rowb + row) * lda + kb + 4 * q);
            As[4 * q + 0][row] = v.x; As[4 * q + 1][row] = v.y;
            As[4 * q + 2][row] = v.z; As[4 * q + 3][row] = v.w;
        }
#pragma unroll
        for (int r = 0; r < 2; r++) {
            int flat = tid + 256 * r;           // 0..511
            int kk = flat >> 4;
            int jq = flat & 15;
            float4 v = *(const float4*)(W + (size_t)(kb + kk) * ldw + colb + 4 * jq);
            *(float4*)&Ws[kk][4 * jq] = v;
        }
        __syncthreads();

#pragma unroll 8
        for (int kk = 0; kk < 32; kk++) {
            float4 av = *(const float4*)&As[kk][4 * ty];
            float4 wv = *(const float4*)&Ws[kk][4 * tx];
            float a[4] = {av.x, av.y, av.z, av.w};
            float w[4] = {wv.x, wv.y, wv.z, wv.w};
#pragma unroll
            for (int i = 0; i < 4; i++)
#pragma unroll
                for (int j = 0; j < 4; j++) acc[i][j] += a[i] * w[j];
        }
    }

#pragma unroll
    for (int i = 0; i < 4; i++) {
        int row = rowb + 4 * ty + i;
#pragma unroll
        for (int j = 0; j < 4; j++) {
            int col = colb + 4 * tx + j;
            float* cp = C + (size_t)row * ldc + coff + col;
            if (ACT == 0) {
                *cp += acc[i][j];
            } else {
                float v = acc[i][j] + bias[col];
                if (ACT == 1) v = v / (1.f + expf(-v));  // silu
                *cp = v;
            }
        }
    }
}

// ---------------- launch ----------------
extern "C" void kernel_launch(void* const* d_in, const int* in_sizes, int n_in,
                              void* d_out, int out_size) {
    const float* x    = (const float*)d_in[0];
    const int*   batch= (const int*)d_in[1];
    const int*   ntm  = (const int*)d_in[2];
    // d_in[3] = num_segments (scalar, fixed = 1024)
    const float* aw1  = (const float*)d_in[4];
    const float* ab1  = (const float*)d_in[5];
    const float* aw2  = (const float*)d_in[6];
    const float* ab2  = (const float*)d_in[7];
    const float* we   = (const float*)d_in[8];
    const float* be   = (const float*)d_in[9];
    const float* wv   = (const float*)d_in[10];
    const float* bv   = (const float*)d_in[11];
    const float* wp   = (const float*)d_in[12];
    const float* bp   = (const float*)d_in[13];
    const float* w1   = (const float*)d_in[14];
    const float* b1   = (const float*)d_in[15];
    const float* w2   = (const float*)d_in[16];
    const float* b2   = (const float*)d_in[17];
    float* out = (float*)d_out;

    // device scratch pointers
    void *p_ts, *p_comb, *p_H, *p_wcat;
    cudaGetSymbolAddress(&p_ts,   g_typesums);
    cudaGetSymbolAddress(&p_comb, g_combined);
    cudaGetSymbolAddress(&p_H,    g_H);
    cudaGetSymbolAddress(&p_wcat, g_wcat);
    float* ts   = (float*)p_ts;
    float* comb = (float*)p_comb;
    float* Hbuf = (float*)p_H;
    float* wcat = (float*)p_wcat;

    k0_bounds<<<(NN + 255) / 256, 256>>>(batch);
    k1_scores<<<(NN + 127) / 128, 256>>>(x, aw1, ab1, aw2, ab2);
    k2_pool<<<BB, 128>>>(x, ntm, be, bv, bp);
    k_cat<<<768, 256>>>(we, wv, wp);

    // phys_pool: combined[:,512:768] += typesums @ wcat  (bias already seeded by k2)
    gemm_k<0><<<dim3(256 / 64, BB / 64), 256>>>(ts, 768, wcat, 256,
                                                comb, 768, 512, nullptr, 768);
    // H = silu(combined @ w1 + b1)
    gemm_k<1><<<dim3(512 / 64, BB / 64), 256>>>(comb, 768, w1, 512,
                                                Hbuf, 512, 0, b1, 768);
    // out = H @ w2 + b2
    gemm_k<2><<<dim3(256 / 64, BB / 64), 256>>>(Hbuf, 512, w2, 256,
                                                out, 256, 0, b2, 512);
}

// round 4
// speedup vs baseline: 1.6304x; 1.6304x over previous
#include <cuda_runtime.h>
#include <cuda_bf16.h>
#include <math.h>
#include <stdint.h>

// Problem constants (fixed shapes)
#define NN 200000
#define DD 256
#define HH 128      // D/2
#define BB 1024
#define OUTD 256
#define NTILES ((NN + 127) / 128)   // 1563

// ---------------- scratch (device globals, no allocation) ----------------
__device__ int   g_segstart[BB + 1];
__device__ float g_s[NN];                 // per-node attention score
__device__ float g_typesums[BB * 768];    // [B][3][256]
__device__ float g_combined[BB * 768];    // [mean | attn | phys]
__device__ float g_H[BB * 512];           // hidden of final MLP
__device__ float g_wcat[768 * 256];       // [we; wv; wp]
__device__ __nv_bfloat16 g_wTh[HH * DD];  // aw1^T hi  [j][k]
__device__ __nv_bfloat16 g_wTl[HH * DD];  // aw1^T lo  [j][k]

__device__ __forceinline__ uint32_t smem_u32(const void* p) {
    uint32_t a;
    asm("{ .reg .u64 t; cvta.to.shared.u64 t, %1; cvt.u32.u64 %0, t; }"
        : "=r"(a) : "l"(p));
    return a;
}

// ---------------- K0: segment boundaries (batch sorted, all segs nonempty)
__global__ void k0_bounds(const int* __restrict__ batch) {
    int i = blockIdx.x * 256 + threadIdx.x;
    if (i < NN) {
        if (i == 0 || batch[i] != batch[i - 1]) g_segstart[batch[i]] = i;
    }
    if (i == 0) g_segstart[BB] = NN;
}

// ---------------- weight prep: aw1 [k][j] fp32 -> transposed split-bf16 [j][k]
__global__ void k_wprep(const float* __restrict__ aw1) {
    int t = blockIdx.x * 256 + threadIdx.x;
    if (t < DD * HH) {
        int k = t >> 7;
        int j = t & 127;
        float w = aw1[t];
        __nv_bfloat16 h = __float2bfloat16(w);
        float hf = __bfloat162float(h);
        __nv_bfloat16 l = __float2bfloat16(w - hf);
        g_wTh[j * DD + k] = h;
        g_wTl[j * DD + k] = l;
    }
}

// ============ K1: scores via mma.sync (HMMA bf16, split precision) ============
// Per tile (128 nodes): D[128n][128j] = Xh@Wh^T + Xl@Wh^T + Xh@Wl^T over K=256
// Then s = tanh(D + ab1) @ aw2 + ab2.
//
// Warp tiling: 8 warps; warp w covers rows (w&3)*32..+32, cols (w>>2)*64..+64.
// Accumulators: 2 m-frags x 8 n-frags x 4 f32 = 64 regs/thread.
//
// smem (dynamic, 1024-aligned base):
//   [0]      aw2s float[128]
//   [512]    ab1s float[128]
//   [1024]   red  float[256]
//   [2048]   Wh   128 rows x 512B (swizzled)      = 64 KB
//   [67584]  Wl   128 rows x 512B                  = 64 KB
//   [133120] Xh   128 rows x 128B (kc chunk, swz)  = 16 KB
//   [149504] Xl   128 rows x 128B                  = 16 KB
#define K1_AW2S 0
#define K1_AB1S 512
#define K1_RED  1024
#define K1_WH   2048
#define K1_WL   (K1_WH + 65536)
#define K1_XH   (K1_WL + 65536)
#define K1_XL   (K1_XH + 16384)
#define K1_SMEM (K1_XL + 16384 + 1024)

#define LDSM_X4(r0, r1, r2, r3, a) \
    asm volatile("ldmatrix.sync.aligned.m8n8.x4.shared.b16 {%0,%1,%2,%3}, [%4];" \
                 : "=r"(r0), "=r"(r1), "=r"(r2), "=r"(r3) : "r"(a))
#define LDSM_X2(r0, r1, a) \
    asm volatile("ldmatrix.sync.aligned.m8n8.x2.shared.b16 {%0,%1}, [%2];" \
                 : "=r"(r0), "=r"(r1) : "r"(a))
#define MMA16816(d, a, b) \
    asm volatile("mma.sync.aligned.m16n8k16.row.col.f32.bf16.bf16.f32 " \
                 "{%0,%1,%2,%3}, {%4,%5,%6,%7}, {%8,%9}, {%0,%1,%2,%3};" \
                 : "+f"((d)[0]), "+f"((d)[1]), "+f"((d)[2]), "+f"((d)[3]) \
                 : "r"((a)[0]), "r"((a)[1]), "r"((a)[2]), "r"((a)[3]), \
                   "r"((b)[0]), "r"((b)[1]))

__global__ __launch_bounds__(256, 1)
void k1_mma(const float* __restrict__ x,
            const float* __restrict__ ab1,
            const float* __restrict__ aw2,
            const float* __restrict__ ab2) {
    extern __shared__ char raw[];
    char* alig = (char*)((((uintptr_t)raw) + 1023) & ~(uintptr_t)1023);
    const uint32_t sb = smem_u32(alig);

    const int tid  = threadIdx.x;
    const int w    = tid >> 5;
    const int lane = tid & 31;
    const int wm   = (w & 3) * 32;      // row base of this warp
    const int jb   = (w >> 2) * 64;     // col base of this warp

    float* aw2s = (float*)(alig + K1_AW2S);
    float* ab1s = (float*)(alig + K1_AB1S);
    float* red  = (float*)(alig + K1_RED);

    if (tid < 128) {
        aw2s[tid] = aw2[tid];
        ab1s[tid] = ab1[tid];
    }
    const float ab2v = ab2[0];

    // ---- weights -> smem once (swizzled rows of 512B) ----
    for (int f = tid; f < 128 * 128; f += 256) {
        int j = f >> 7;
        int k = (f & 127) * 2;                       // even k; b32 = {k, k+1}
        uint32_t dst = (uint32_t)(j * 512 + ((k * 2) ^ ((j & 7) << 4)));
        *(uint32_t*)(alig + K1_WH + dst) =
            *(const uint32_t*)((const char*)g_wTh + (j * DD + k) * 2);
        *(uint32_t*)(alig + K1_WL + dst) =
            *(const uint32_t*)((const char*)g_wTl + (j * DD + k) * 2);
    }
    __syncthreads();

    // ldmatrix lane-address components (constant per thread)
    // A (x4): lanes 0-15 -> rows +(l&15), koff 0; lanes 16-31 -> same rows, +16B
    const int arow_off = lane & 15;
    const int akoff    = (lane >> 4) << 4;
    // B (x2): lanes 0-7 -> rows, +0; lanes 8-15 -> rows, +16B
    const int brow_off = lane & 7;
    const int bkoff    = (lane & 8) << 1;

    for (int t = blockIdx.x; t < NTILES; t += gridDim.x) {
        const int base = t * 128;

        float acc[2][8][4];
#pragma unroll
        for (int mi = 0; mi < 2; mi++)
#pragma unroll
            for (int ni = 0; ni < 8; ni++)
#pragma unroll
                for (int q = 0; q < 4; q++) acc[mi][ni][q] = 0.f;

        // register prefetch buffer: 8 float4 per thread = one 128x64 chunk
        float4 pv[8];
        {
            const int kc64 = 0;
#pragma unroll
            for (int r = 0; r < 8; r++) {
                int f = tid + 256 * r;
                int row = f >> 4, q = f & 15;
                int node = base + row;
                pv[r] = (node < NN)
                    ? *(const float4*)(x + (size_t)node * DD + kc64 + q * 4)
                    : make_float4(0.f, 0.f, 0.f, 0.f);
            }
        }

        for (int kc = 0; kc < 4; kc++) {
            // ---- convert prefetched chunk into Xh/Xl (swizzled) ----
#pragma unroll
            for (int r = 0; r < 8; r++) {
                int f = tid + 256 * r;
                int row = f >> 4, q = f & 15;
                float4 v = pv[r];
                uint32_t h0, h1, l0, l1;
                asm("cvt.rn.bf16x2.f32 %0, %1, %2;" : "=r"(h0) : "f"(v.y), "f"(v.x));
                asm("cvt.rn.bf16x2.f32 %0, %1, %2;" : "=r"(h1) : "f"(v.w), "f"(v.z));
                float f0 = __int_as_float(h0 << 16);
                float f1 = __int_as_float(h0 & 0xFFFF0000u);
                float f2 = __int_as_float(h1 << 16);
                float f3 = __int_as_float(h1 & 0xFFFF0000u);
                asm("cvt.rn.bf16x2.f32 %0, %1, %2;" : "=r"(l0) : "f"(v.y - f1), "f"(v.x - f0));
                asm("cvt.rn.bf16x2.f32 %0, %1, %2;" : "=r"(l1) : "f"(v.w - f3), "f"(v.z - f2));
                uint32_t s0 = (uint32_t)(row * 128 + ((q * 8) ^ ((row & 7) << 4)));
                *(uint32_t*)(alig + K1_XH + s0)     = h0;
                *(uint32_t*)(alig + K1_XH + s0 + 4) = h1;
                *(uint32_t*)(alig + K1_XL + s0)     = l0;
                *(uint32_t*)(alig + K1_XL + s0 + 4) = l1;
            }
            __syncthreads();

            // ---- prefetch next chunk while MMAs run ----
            if (kc < 3) {
                const int kc64 = (kc + 1) * 64;
#pragma unroll
                for (int r = 0; r < 8; r++) {
                    int f = tid + 256 * r;
                    int row = f >> 4, q = f & 15;
                    int node = base + row;
                    pv[r] = (node < NN)
                        ? *(const float4*)(x + (size_t)node * DD + kc64 + q * 4)
                        : make_float4(0.f, 0.f, 0.f, 0.f);
                }
            }

            // ---- MMA over this 64-wide K chunk (4 k16 steps) ----
#pragma unroll
            for (int ks = 0; ks < 4; ks++) {
                const int kb = ks * 32;                 // byte offset in X row
                const int wkb = kc * 128 + kb;          // byte offset in W row

                uint32_t ah[2][4], al[2][4];
#pragma unroll
                for (int mi = 0; mi < 2; mi++) {
                    int row = wm + mi * 16 + arow_off;
                    uint32_t ao = (uint32_t)(row * 128 +
                        ((kb + akoff) ^ ((row & 7) << 4)));
                    LDSM_X4(ah[mi][0], ah[mi][1], ah[mi][2], ah[mi][3],
                            sb + K1_XH + ao);
                    LDSM_X4(al[mi][0], al[mi][1], al[mi][2], al[mi][3],
                            sb + K1_XL + ao);
                }
                uint32_t bh[8][2], bl[8][2];
#pragma unroll
                for (int ni = 0; ni < 8; ni++) {
                    int jrow = jb + ni * 8 + brow_off;
                    uint32_t bo = (uint32_t)(jrow * 512 +
                        ((wkb + bkoff) ^ ((jrow & 7) << 4)));
                    LDSM_X2(bh[ni][0], bh[ni][1], sb + K1_WH + bo);
                    LDSM_X2(bl[ni][0], bl[ni][1], sb + K1_WL + bo);
                }
#pragma unroll
                for (int mi = 0; mi < 2; mi++)
#pragma unroll
                    for (int ni = 0; ni < 8; ni++) {
                        MMA16816(acc[mi][ni], ah[mi], bh[ni]);
                        MMA16816(acc[mi][ni], al[mi], bh[ni]);
                        MMA16816(acc[mi][ni], ah[mi], bl[ni]);
                    }
            }
            __syncthreads();
        }

        // ---- epilogue: s = tanh(acc + ab1) @ aw2, reduce, write ----
#pragma unroll
        for (int mi = 0; mi < 2; mi++) {
            float plo = 0.f, phi = 0.f;
#pragma unroll
            for (int ni = 0; ni < 8; ni++) {
                int c0 = jb + ni * 8 + (lane & 3) * 2;
                float w0 = aw2s[c0], w1 = aw2s[c0 + 1];
                float b0 = ab1s[c0], b1 = ab1s[c0 + 1];
                plo += tanhf(acc[mi][ni][0] + b0) * w0
                     + tanhf(acc[mi][ni][1] + b1) * w1;
                phi += tanhf(acc[mi][ni][2] + b0) * w0
                     + tanhf(acc[mi][ni][3] + b1) * w1;
            }
            plo += __shfl_xor_sync(0xFFFFFFFFu, plo, 1);
            plo += __shfl_xor_sync(0xFFFFFFFFu, plo, 2);
            phi += __shfl_xor_sync(0xFFFFFFFFu, phi, 1);
            phi += __shfl_xor_sync(0xFFFFFFFFu, phi, 2);
            if ((lane & 3) == 0) {
                int rlo = wm + mi * 16 + (lane >> 2);
                red[(w >> 2) * 128 + rlo]     = plo;
                red[(w >> 2) * 128 + rlo + 8] = phi;
            }
        }
        __syncthreads();
        if (tid < 128) {
            int node = base + tid;
            if (node < NN) g_s[node] = red[tid] + red[128 + tid] + ab2v;
        }
        __syncthreads();
    }
}

// ---------------- K2: per-segment softmax stats + all pools (one x pass)
__global__ __launch_bounds__(128)
void k2_pool(const float* __restrict__ x,
             const int* __restrict__ ntm,
             const float* __restrict__ be,
             const float* __restrict__ bv,
             const float* __restrict__ bp) {
    const int b = blockIdx.x;
    const int tid = threadIdx.x;
    const int st = g_segstart[b];
    const int en = g_segstart[b + 1];

    __shared__ float red[128];

    float m = -1e30f;
    for (int i = st + tid; i < en; i += 128) m = fmaxf(m, g_s[i]);
    red[tid] = m; __syncthreads();
    for (int off = 64; off > 0; off >>= 1) {
        if (tid < off) red[tid] = fmaxf(red[tid], red[tid + off]);
        __syncthreads();
    }
    m = red[0]; __syncthreads();

    float z = 0.f;
    for (int i = st + tid; i < en; i += 128) z += expf(g_s[i] - m);
    red[tid] = z; __syncthreads();
    for (int off = 64; off > 0; off >>= 1) {
        if (tid < off) red[tid] += red[tid + off];
        __syncthreads();
    }
    z = red[0]; __syncthreads();
    float inv_z = 1.f / z;

    const int d0 = tid * 2;
    float am0 = 0.f, am1 = 0.f, aa0 = 0.f, aa1 = 0.f;
    float t00 = 0.f, t01 = 0.f, t10 = 0.f, t11 = 0.f, t20 = 0.f, t21 = 0.f;
    int c0 = 0, c1 = 0, c2 = 0;

    for (int i = st; i < en; i++) {
        float wgt = expf(g_s[i] - m) * inv_z;
        int tt = ntm[i * 3 + 1] + 2 * ntm[i * 3 + 2];
        float2 xv = *(const float2*)(x + (size_t)i * DD + d0);
        am0 += xv.x; am1 += xv.y;
        aa0 += wgt * xv.x; aa1 += wgt * xv.y;
        if (tt == 0)      { t00 += xv.x; t01 += xv.y; c0++; }
        else if (tt == 1) { t10 += xv.x; t11 += xv.y; c1++; }
        else              { t20 += xv.x; t21 += xv.y; c2++; }
    }

    float invc = 1.f / (float)(en - st);
    float* comb = g_combined + (size_t)b * 768;
    comb[d0]       = am0 * invc;  comb[d0 + 1]       = am1 * invc;
    comb[256 + d0] = aa0;         comb[256 + d0 + 1] = aa1;

    float* ts = g_typesums + (size_t)b * 768;
    ts[d0]           = t00; ts[d0 + 1]           = t01;
    ts[256 + d0]     = t10; ts[256 + d0 + 1]     = t11;
    ts[512 + d0]     = t20; ts[512 + d0 + 1]     = t21;

    float f0 = (float)c0, f1 = (float)c1, f2 = (float)c2;
    comb[512 + d0]     = f0 * be[d0]     + f1 * bv[d0]     + f2 * bp[d0];
    comb[512 + d0 + 1] = f0 * be[d0 + 1] + f1 * bv[d0 + 1] + f2 * bp[d0 + 1];
}

// ---------------- weight concat [we; wv; wp] -> g_wcat[768][256]
__global__ void k_cat(const float* __restrict__ we,
                      const float* __restrict__ wv,
                      const float* __restrict__ wp) {
    int t = blockIdx.x * 256 + threadIdx.x;
    if (t < 768 * 256) {
        int k = t >> 8;
        int n = t & 255;
        float v;
        if (k < 256)      v = we[k * 256 + n];
        else if (k < 512) v = wv[(k - 256) * 256 + n];
        else              v = wp[(k - 512) * 256 + n];
        g_wcat[t] = v;
    }
}

// ---------------- generic tiled GEMM: C = act(A[M][K] @ W[K][N] + bias)
template <int ACT>
__global__ __launch_bounds__(256)
void gemm_k(const float* __restrict__ A, int lda,
            const float* __restrict__ W, int ldw,
            float* __restrict__ C, int ldc, int coff,
            const float* __restrict__ bias, int Kdim) {
    __shared__ float As[32][64];
    __shared__ float Ws[32][64];

    const int tid = threadIdx.x;
    const int tx = tid & 15;
    const int ty = tid >> 4;
    const int colb = blockIdx.x * 64;
    const int rowb = blockIdx.y * 64;

    float acc[4][4];
#pragma unroll
    for (int i = 0; i < 4; i++)
#pragma unroll
        for (int j = 0; j < 4; j++) acc[i][j] = 0.f;

    for (int kb = 0; kb < Kdim; kb += 32) {
        __syncthreads();
#pragma unroll
        for (int r = 0; r < 2; r++) {
            int flat = tid + 256 * r;
            int row = flat >> 3;
            int q = flat & 7;
            float4 v = *(const float4*)(A + (size_t)(rowb + row) * lda + kb + 4 * q);
            As[4 * q + 0][row] = v.x; As[4 * q + 1][row] = v.y;
            As[4 * q + 2][row] = v.z; As[4 * q + 3][row] = v.w;
        }
#pragma unroll
        for (int r = 0; r < 2; r++) {
            int flat = tid + 256 * r;
            int kk = flat >> 4;
            int jq = flat & 15;
            float4 v = *(const float4*)(W + (size_t)(kb + kk) * ldw + colb + 4 * jq);
            *(float4*)&Ws[kk][4 * jq] = v;
        }
        __syncthreads();

#pragma unroll 8
        for (int kk = 0; kk < 32; kk++) {
            float4 av = *(const float4*)&As[kk][4 * ty];
            float4 wv = *(const float4*)&Ws[kk][4 * tx];
            float a[4] = {av.x, av.y, av.z, av.w};
            float wr[4] = {wv.x, wv.y, wv.z, wv.w};
#pragma unroll
            for (int i = 0; i < 4; i++)
#pragma unroll
                for (int j = 0; j < 4; j++) acc[i][j] += a[i] * wr[j];
        }
    }

#pragma unroll
    for (int i = 0; i < 4; i++) {
        int row = rowb + 4 * ty + i;
#pragma unroll
        for (int j = 0; j < 4; j++) {
            int col = colb + 4 * tx + j;
            float* cp = C + (size_t)row * ldc + coff + col;
            if (ACT == 0) {
                *cp += acc[i][j];
            } else {
                float v = acc[i][j] + bias[col];
                if (ACT == 1) v = v / (1.f + expf(-v));  // silu
                *cp = v;
            }
        }
    }
}

// ---------------- launch ----------------
extern "C" void kernel_launch(void* const* d_in, const int* in_sizes, int n_in,
                              void* d_out, int out_size) {
    const float* x    = (const float*)d_in[0];
    const int*   batch= (const int*)d_in[1];
    const int*   ntm  = (const int*)d_in[2];
    const float* aw1  = (const float*)d_in[4];
    const float* ab1  = (const float*)d_in[5];
    const float* aw2  = (const float*)d_in[6];
    const float* ab2  = (const float*)d_in[7];
    const float* we   = (const float*)d_in[8];
    const float* be   = (const float*)d_in[9];
    const float* wv   = (const float*)d_in[10];
    const float* bv   = (const float*)d_in[11];
    const float* wp   = (const float*)d_in[12];
    const float* bp   = (const float*)d_in[13];
    const float* w1   = (const float*)d_in[14];
    const float* b1   = (const float*)d_in[15];
    const float* w2   = (const float*)d_in[16];
    const float* b2   = (const float*)d_in[17];
    float* out = (float*)d_out;

    void *p_ts, *p_comb, *p_H, *p_wcat;
    cudaGetSymbolAddress(&p_ts,   g_typesums);
    cudaGetSymbolAddress(&p_comb, g_combined);
    cudaGetSymbolAddress(&p_H,    g_H);
    cudaGetSymbolAddress(&p_wcat, g_wcat);
    float* ts   = (float*)p_ts;
    float* comb = (float*)p_comb;
    float* Hbuf = (float*)p_H;
    float* wcat = (float*)p_wcat;

    cudaFuncSetAttribute(k1_mma, cudaFuncAttributeMaxDynamicSharedMemorySize, K1_SMEM);

    k0_bounds<<<(NN + 255) / 256, 256>>>(batch);
    k_wprep<<<(DD * HH + 255) / 256, 256>>>(aw1);
    k1_mma<<<148, 256, K1_SMEM>>>(x, ab1, aw2, ab2);
    k2_pool<<<BB, 128>>>(x, ntm, be, bv, bp);
    k_cat<<<768, 256>>>(we, wv, wp);

    // phys_pool: combined[:,512:768] += typesums @ wcat
    gemm_k<0><<<dim3(256 / 64, BB / 64), 256>>>(ts, 768, wcat, 256,
                                                comb, 768, 512, nullptr, 768);
    // H = silu(combined @ w1 + b1)
    gemm_k<1><<<dim3(512 / 64, BB / 64), 256>>>(comb, 768, w1, 512,
                                                Hbuf, 512, 0, b1, 768);
    // out = H @ w2 + b2
    gemm_k<2><<<dim3(256 / 64, BB / 64), 256>>>(Hbuf, 512, w2, 256,
                                                out, 256, 0, b2, 512);
}

// round 8
// speedup vs baseline: 1.9029x; 1.1671x over previous
#include <cuda_runtime.h>
#include <cuda_bf16.h>
#include <math.h>
#include <stdint.h>

// Problem constants (fixed shapes)
#define NN 200000
#define DD 256
#define HH 128      // D/2
#define BB 1024
#define OUTD 256
#define NTILES ((NN + 127) / 128)   // 1563

// ---------------- scratch (device globals, no allocation) ----------------
__device__ int   g_segstart[BB + 1];
__device__ float g_s[NN];                 // per-node attention score
__device__ uint8_t g_t8[NN];              // per-node type 0/1/2
__device__ float g_m[BB];                 // segment max of s
__device__ float g_iz[BB];                // 1 / segment sum exp
__device__ float g_cnt[BB * 4];           // c0, c1, c2, 1/count
__device__ float g_typesums[BB * 768];    // [B][3][256]
__device__ float g_combined[BB * 768];    // [mean | attn | phys]
__device__ float g_H[BB * 512];           // hidden of final MLP
__device__ float g_wcat[768 * 256];       // [we; wv; wp]
__device__ __nv_bfloat16 g_wTh[HH * DD];  // aw1^T hi  [j][k]
__device__ __nv_bfloat16 g_wTl[HH * DD];  // aw1^T lo  [j][k]

__device__ __forceinline__ uint32_t smem_u32(const void* p) {
    uint32_t a;
    asm("{ .reg .u64 t; cvta.to.shared.u64 t, %1; cvt.u32.u64 %0, t; }"
        : "=r"(a) : "l"(p));
    return a;
}

// ---------------- K0: segment boundaries + packed node type
__global__ void k0_bounds(const int* __restrict__ batch,
                          const int* __restrict__ ntm) {
    int i = blockIdx.x * 256 + threadIdx.x;
    if (i < NN) {
        if (i == 0 || batch[i] != batch[i - 1]) g_segstart[batch[i]] = i;
        g_t8[i] = (uint8_t)(ntm[i * 3 + 1] + 2 * ntm[i * 3 + 2]);
    }
    if (i == 0) g_segstart[BB] = NN;
}

// ---------------- weight prep: aw1 [k][j] fp32 -> transposed split-bf16 [j][k]
__global__ void k_wprep(const float* __restrict__ aw1) {
    int t = blockIdx.x * 256 + threadIdx.x;
    if (t < DD * HH) {
        int k = t >> 7;
        int j = t & 127;
        float w = aw1[t];
        __nv_bfloat16 h = __float2bfloat16(w);
        float hf = __bfloat162float(h);
        __nv_bfloat16 l = __float2bfloat16(w - hf);
        g_wTh[j * DD + k] = h;
        g_wTl[j * DD + k] = l;
    }
}

// ============ K1: scores via mma.sync (HMMA bf16, split precision) ============
#define K1_AW2S 0
#define K1_AB1S 512
#define K1_RED  1024
#define K1_WH   2048
#define K1_WL   (K1_WH + 65536)
#define K1_XH   (K1_WL + 65536)
#define K1_XL   (K1_XH + 16384)
#define K1_SMEM (K1_XL + 16384 + 1024)

#define LDSM_X4(r0, r1, r2, r3, a) \
    asm volatile("ldmatrix.sync.aligned.m8n8.x4.shared.b16 {%0,%1,%2,%3}, [%4];" \
                 : "=r"(r0), "=r"(r1), "=r"(r2), "=r"(r3) : "r"(a))
#define LDSM_X2(r0, r1, a) \
    asm volatile("ldmatrix.sync.aligned.m8n8.x2.shared.b16 {%0,%1}, [%2];" \
                 : "=r"(r0), "=r"(r1) : "r"(a))
#define MMA16816(d, a, b) \
    asm volatile("mma.sync.aligned.m16n8k16.row.col.f32.bf16.bf16.f32 " \
                 "{%0,%1,%2,%3}, {%4,%5,%6,%7}, {%8,%9}, {%0,%1,%2,%3};" \
                 : "+f"((d)[0]), "+f"((d)[1]), "+f"((d)[2]), "+f"((d)[3]) \
                 : "r"((a)[0]), "r"((a)[1]), "r"((a)[2]), "r"((a)[3]), \
                   "r"((b)[0]), "r"((b)[1]))

__global__ __launch_bounds__(256, 1)
void k1_mma(const float* __restrict__ x,
            const float* __restrict__ ab1,
            const float* __restrict__ aw2,
            const float* __restrict__ ab2) {
    extern __shared__ char raw[];
    char* alig = (char*)((((uintptr_t)raw) + 1023) & ~(uintptr_t)1023);
    const uint32_t sb = smem_u32(alig);

    const int tid  = threadIdx.x;
    const int w    = tid >> 5;
    const int lane = tid & 31;
    const int wm   = (w & 3) * 32;      // row base of this warp
    const int jb   = (w >> 2) * 64;     // col base of this warp

    float* aw2s = (float*)(alig + K1_AW2S);
    float* ab1s = (float*)(alig + K1_AB1S);
    float* red  = (float*)(alig + K1_RED);

    if (tid < 128) {
        aw2s[tid] = aw2[tid];
        ab1s[tid] = ab1[tid];
    }
    const float ab2v = ab2[0];

    // ---- weights -> smem once (swizzled rows of 512B) ----
    for (int f = tid; f < 128 * 128; f += 256) {
        int j = f >> 7;
        int k = (f & 127) * 2;
        uint32_t dst = (uint32_t)(j * 512 + ((k * 2) ^ ((j & 7) << 4)));
        *(uint32_t*)(alig + K1_WH + dst) =
            *(const uint32_t*)((const char*)g_wTh + (j * DD + k) * 2);
        *(uint32_t*)(alig + K1_WL + dst) =
            *(const uint32_t*)((const char*)g_wTl + (j * DD + k) * 2);
    }
    __syncthreads();

    const int arow_off = lane & 15;
    const int akoff    = (lane >> 4) << 4;
    const int brow_off = lane & 7;
    const int bkoff    = (lane & 8) << 1;

    for (int t = blockIdx.x; t < NTILES; t += gridDim.x) {
        const int base = t * 128;

        float acc[2][8][4];
#pragma unroll
        for (int mi = 0; mi < 2; mi++)
#pragma unroll
            for (int ni = 0; ni < 8; ni++)
#pragma unroll
                for (int q = 0; q < 4; q++) acc[mi][ni][q] = 0.f;

        float4 pv[8];
        {
#pragma unroll
            for (int r = 0; r < 8; r++) {
                int f = tid + 256 * r;
                int row = f >> 4, q = f & 15;
                int node = base + row;
                pv[r] = (node < NN)
                    ? *(const float4*)(x + (size_t)node * DD + q * 4)
                    : make_float4(0.f, 0.f, 0.f, 0.f);
            }
        }

        for (int kc = 0; kc < 4; kc++) {
#pragma unroll
            for (int r = 0; r < 8; r++) {
                int f = tid + 256 * r;
                int row = f >> 4, q = f & 15;
                float4 v = pv[r];
                uint32_t h0, h1, l0, l1;
                asm("cvt.rn.bf16x2.f32 %0, %1, %2;" : "=r"(h0) : "f"(v.y), "f"(v.x));
                asm("cvt.rn.bf16x2.f32 %0, %1, %2;" : "=r"(h1) : "f"(v.w), "f"(v.z));
                float f0 = __int_as_float(h0 << 16);
                float f1 = __int_as_float(h0 & 0xFFFF0000u);
                float f2 = __int_as_float(h1 << 16);
                float f3 = __int_as_float(h1 & 0xFFFF0000u);
                asm("cvt.rn.bf16x2.f32 %0, %1, %2;" : "=r"(l0) : "f"(v.y - f1), "f"(v.x - f0));
                asm("cvt.rn.bf16x2.f32 %0, %1, %2;" : "=r"(l1) : "f"(v.w - f3), "f"(v.z - f2));
                uint32_t s0 = (uint32_t)(row * 128 + ((q * 8) ^ ((row & 7) << 4)));
                *(uint32_t*)(alig + K1_XH + s0)     = h0;
                *(uint32_t*)(alig + K1_XH + s0 + 4) = h1;
                *(uint32_t*)(alig + K1_XL + s0)     = l0;
                *(uint32_t*)(alig + K1_XL + s0 + 4) = l1;
            }
            __syncthreads();

            if (kc < 3) {
                const int kc64 = (kc + 1) * 64;
#pragma unroll
                for (int r = 0; r < 8; r++) {
                    int f = tid + 256 * r;
                    int row = f >> 4, q = f & 15;
                    int node = base + row;
                    pv[r] = (node < NN)
                        ? *(const float4*)(x + (size_t)node * DD + kc64 + q * 4)
                        : make_float4(0.f, 0.f, 0.f, 0.f);
                }
            }

#pragma unroll
            for (int ks = 0; ks < 4; ks++) {
                const int kb = ks * 32;
                const int wkb = kc * 128 + kb;

                uint32_t ah[2][4], al[2][4];
#pragma unroll
                for (int mi = 0; mi < 2; mi++) {
                    int row = wm + mi * 16 + arow_off;
                    uint32_t ao = (uint32_t)(row * 128 +
                        ((kb + akoff) ^ ((row & 7) << 4)));
                    LDSM_X4(ah[mi][0], ah[mi][1], ah[mi][2], ah[mi][3],
                            sb + K1_XH + ao);
                    LDSM_X4(al[mi][0], al[mi][1], al[mi][2], al[mi][3],
                            sb + K1_XL + ao);
                }
                uint32_t bh[8][2], bl[8][2];
#pragma unroll
                for (int ni = 0; ni < 8; ni++) {
                    int jrow = jb + ni * 8 + brow_off;
                    uint32_t bo = (uint32_t)(jrow * 512 +
                        ((wkb + bkoff) ^ ((jrow & 7) << 4)));
                    LDSM_X2(bh[ni][0], bh[ni][1], sb + K1_WH + bo);
                    LDSM_X2(bl[ni][0], bl[ni][1], sb + K1_WL + bo);
                }
#pragma unroll
                for (int mi = 0; mi < 2; mi++)
#pragma unroll
                    for (int ni = 0; ni < 8; ni++) {
                        MMA16816(acc[mi][ni], ah[mi], bh[ni]);
                        MMA16816(acc[mi][ni], al[mi], bh[ni]);
                        MMA16816(acc[mi][ni], ah[mi], bl[ni]);
                    }
            }
            __syncthreads();
        }

        // ---- epilogue: s = tanh(acc + ab1) @ aw2, reduce, write ----
#pragma unroll
        for (int mi = 0; mi < 2; mi++) {
            float plo = 0.f, phi = 0.f;
#pragma unroll
            for (int ni = 0; ni < 8; ni++) {
                int c0 = jb + ni * 8 + (lane & 3) * 2;
                float w0 = aw2s[c0], w1 = aw2s[c0 + 1];
                float b0 = ab1s[c0], b1 = ab1s[c0 + 1];
                plo += tanhf(acc[mi][ni][0] + b0) * w0
                     + tanhf(acc[mi][ni][1] + b1) * w1;
                phi += tanhf(acc[mi][ni][2] + b0) * w0
                     + tanhf(acc[mi][ni][3] + b1) * w1;
            }
            plo += __shfl_xor_sync(0xFFFFFFFFu, plo, 1);
            plo += __shfl_xor_sync(0xFFFFFFFFu, plo, 2);
            phi += __shfl_xor_sync(0xFFFFFFFFu, phi, 1);
            phi += __shfl_xor_sync(0xFFFFFFFFu, phi, 2);
            if ((lane & 3) == 0) {
                int rlo = wm + mi * 16 + (lane >> 2);
                red[(w >> 2) * 128 + rlo]     = plo;
                red[(w >> 2) * 128 + rlo + 8] = phi;
            }
        }
        __syncthreads();
        if (tid < 128) {
            int node = base + tid;
            if (node < NN) g_s[node] = red[tid] + red[128 + tid] + ab2v;
        }
        __syncthreads();
    }
}

// ---------------- K2a: per-segment stats (m, 1/z, type counts, 1/count)
__global__ __launch_bounds__(128)
void k2a_stats() {
    const int b = blockIdx.x;
    const int tid = threadIdx.x;
    const int st = g_segstart[b];
    const int en = g_segstart[b + 1];

    __shared__ float red[128];
    __shared__ int   redi[128];

    float m = -1e30f;
    int cp = 0;                               // c0 | c1<<10 | c2<<20
    for (int i = st + tid; i < en; i += 128) {
        m = fmaxf(m, g_s[i]);
        int t = g_t8[i];
        cp += 1 << (t * 10);
    }
    red[tid] = m; redi[tid] = cp; __syncthreads();
    for (int off = 64; off > 0; off >>= 1) {
        if (tid < off) {
            red[tid] = fmaxf(red[tid], red[tid + off]);
            redi[tid] += redi[tid + off];
        }
        __syncthreads();
    }
    m = red[0]; cp = redi[0]; __syncthreads();

    float z = 0.f;
    for (int i = st + tid; i < en; i += 128) z += expf(g_s[i] - m);
    red[tid] = z; __syncthreads();
    for (int off = 64; off > 0; off >>= 1) {
        if (tid < off) red[tid] += red[tid + off];
        __syncthreads();
    }
    if (tid == 0) {
        g_m[b]  = m;
        g_iz[b] = 1.f / red[0];
        g_cnt[b * 4 + 0] = (float)(cp & 1023);
        g_cnt[b * 4 + 1] = (float)((cp >> 10) & 1023);
        g_cnt[b * 4 + 2] = (float)((cp >> 20) & 1023);
        g_cnt[b * 4 + 3] = 1.f / (float)(en - st);
    }
}

// ---------------- K2b: pools. 512 thr = 4 i-groups x 128 column-threads.
__global__ __launch_bounds__(512)
void k2b_pool(const float* __restrict__ x,
              const float* __restrict__ be,
              const float* __restrict__ bv,
              const float* __restrict__ bp) {
    const int b   = blockIdx.x;
    const int tid = threadIdx.x;
    const int g   = tid >> 7;        // i-group 0..3
    const int col = tid & 127;       // column pair index
    const int d0  = col * 2;
    const int st  = g_segstart[b];
    const int en  = g_segstart[b + 1];
    const float m  = g_m[b];
    const float iz = g_iz[b];

    __shared__ float sred[512 * 10];  // 20 KB

    float a0 = 0.f, a1 = 0.f, w0 = 0.f, w1 = 0.f;
    float t00 = 0.f, t01 = 0.f, t10 = 0.f, t11 = 0.f, t20 = 0.f, t21 = 0.f;

    const float* xp = x + d0;

    int i = st + g;
    // unrolled by 2 (group stride 4)
    for (; i + 4 < en; i += 8) {
        float  s0 = g_s[i],      s1 = g_s[i + 4];
        int    ty0 = g_t8[i],    ty1 = g_t8[i + 4];
        float2 v0 = *(const float2*)(xp + (size_t)i * DD);
        float2 v1 = *(const float2*)(xp + (size_t)(i + 4) * DD);
        float  e0 = expf(s0 - m) * iz;
        float  e1 = expf(s1 - m) * iz;

        a0 += v0.x + v1.x;  a1 += v0.y + v1.y;
        w0 = fmaf(e0, v0.x, w0); w0 = fmaf(e1, v1.x, w0);
        w1 = fmaf(e0, v0.y, w1); w1 = fmaf(e1, v1.y, w1);

        float m00 = (ty0 == 0), m01 = (ty0 == 1), m02 = (ty0 == 2);
        float m10 = (ty1 == 0), m11 = (ty1 == 1), m12 = (ty1 == 2);
        t00 = fmaf(m00, v0.x, t00); t00 = fmaf(m10, v1.x, t00);
        t01 = fmaf(m00, v0.y, t01); t01 = fmaf(m10, v1.y, t01);
        t10 = fmaf(m01, v0.x, t10); t10 = fmaf(m11, v1.x, t10);
        t11 = fmaf(m01, v0.y, t11); t11 = fmaf(m11, v1.y, t11);
        t20 = fmaf(m02, v0.x, t20); t20 = fmaf(m12, v1.x, t20);
        t21 = fmaf(m02, v0.y, t21); t21 = fmaf(m12, v1.y, t21);
    }
    for (; i < en; i += 4) {
        float  s0 = g_s[i];
        int    ty0 = g_t8[i];
        float2 v0 = *(const float2*)(xp + (size_t)i * DD);
        float  e0 = expf(s0 - m) * iz;
        a0 += v0.x; a1 += v0.y;
        w0 = fmaf(e0, v0.x, w0); w1 = fmaf(e0, v0.y, w1);
        float m00 = (ty0 == 0), m01 = (ty0 == 1), m02 = (ty0 == 2);
        t00 = fmaf(m00, v0.x, t00); t01 = fmaf(m00, v0.y, t01);
        t10 = fmaf(m01, v0.x, t10); t11 = fmaf(m01, v0.y, t11);
        t20 = fmaf(m02, v0.x, t20); t21 = fmaf(m02, v0.y, t21);
    }

    float* sp = sred + tid * 10;
    sp[0] = a0;  sp[1] = a1;  sp[2] = w0;  sp[3] = w1;
    sp[4] = t00; sp[5] = t01; sp[6] = t10; sp[7] = t11;
    sp[8] = t20; sp[9] = t21;
    __syncthreads();

    if (tid < 128) {
        float r[10];
#pragma unroll
        for (int q = 0; q < 10; q++) r[q] = sred[tid * 10 + q];
#pragma unroll
        for (int gg = 1; gg < 4; gg++)
#pragma unroll
            for (int q = 0; q < 10; q++) r[q] += sred[(gg * 128 + tid) * 10 + q];

        float f0   = g_cnt[b * 4 + 0];
        float f1   = g_cnt[b * 4 + 1];
        float f2   = g_cnt[b * 4 + 2];
        float invc = g_cnt[b * 4 + 3];

        float* comb = g_combined + (size_t)b * 768;
        comb[d0]           = r[0] * invc;  comb[d0 + 1]       = r[1] * invc;
        comb[256 + d0]     = r[2];         comb[256 + d0 + 1] = r[3];

        float* ts = g_typesums + (size_t)b * 768;
        ts[d0]           = r[4]; ts[d0 + 1]       = r[5];
        ts[256 + d0]     = r[6]; ts[256 + d0 + 1] = r[7];
        ts[512 + d0]     = r[8]; ts[512 + d0 + 1] = r[9];

        comb[512 + d0]     = f0 * be[d0]     + f1 * bv[d0]     + f2 * bp[d0];
        comb[512 + d0 + 1] = f0 * be[d0 + 1] + f1 * bv[d0 + 1] + f2 * bp[d0 + 1];
    }
}

// ---------------- weight concat [we; wv; wp] -> g_wcat[768][256]
__global__ void k_cat(const float* __restrict__ we,
                      const float* __restrict__ wv,
                      const float* __restrict__ wp) {
    int t = blockIdx.x * 256 + threadIdx.x;
    if (t < 768 * 256) {
        int k = t >> 8;
        int n = t & 255;
        float v;
        if (k < 256)      v = we[k * 256 + n];
        else if (k < 512) v = wv[(k - 256) * 256 + n];
        else              v = wp[(k - 512) * 256 + n];
        g_wcat[t] = v;
    }
}

// ---------------- generic tiled GEMM: C = act(A[M][K] @ W[K][N] + bias)
template <int ACT>
__global__ __launch_bounds__(256)
void gemm_k(const float* __restrict__ A, int lda,
            const float* __restrict__ W, int ldw,
            float* __restrict__ C, int ldc, int coff,
            const float* __restrict__ bias, int Kdim) {
    __shared__ float As[32][64];
    __shared__ float Ws[32][64];

    const int tid = threadIdx.x;
    const int tx = tid & 15;
    const int ty = tid >> 4;
    const int colb = blockIdx.x * 64;
    const int rowb = blockIdx.y * 64;

    float acc[4][4];
#pragma unroll
    for (int i = 0; i < 4; i++)
#pragma unroll
        for (int j = 0; j < 4; j++) acc[i][j] = 0.f;

    for (int kb = 0; kb < Kdim; kb += 32) {
        __syncthreads();
#pragma unroll
        for (int r = 0; r < 2; r++) {
            int flat = tid + 256 * r;
            int row = flat >> 3;
            int q = flat & 7;
            float4 v = *(const float4*)(A + (size_t)(rowb + row) * lda + kb + 4 * q);
            As[4 * q + 0][row] = v.x; As[4 * q + 1][row] = v.y;
            As[4 * q + 2][row] = v.z; As[4 * q + 3][row] = v.w;
        }
#pragma unroll
        for (int r = 0; r < 2; r++) {
            int flat = tid + 256 * r;
            int kk = flat >> 4;
            int jq = flat & 15;
            float4 v = *(const float4*)(W + (size_t)(kb + kk) * ldw + colb + 4 * jq);
            *(float4*)&Ws[kk][4 * jq] = v;
        }
        __syncthreads();

#pragma unroll 8
        for (int kk = 0; kk < 32; kk++) {
            float4 av = *(const float4*)&As[kk][4 * ty];
            float4 wv = *(const float4*)&Ws[kk][4 * tx];
            float a[4] = {av.x, av.y, av.z, av.w};
            float wr[4] = {wv.x, wv.y, wv.z, wv.w};
#pragma unroll
            for (int i = 0; i < 4; i++)
#pragma unroll
                for (int j = 0; j < 4; j++) acc[i][j] += a[i] * wr[j];
        }
    }

#pragma unroll
    for (int i = 0; i < 4; i++) {
        int row = rowb + 4 * ty + i;
#pragma unroll
        for (int j = 0; j < 4; j++) {
            int col = colb + 4 * tx + j;
            float* cp = C + (size_t)row * ldc + coff + col;
            if (ACT == 0) {
                *cp += acc[i][j];
            } else {
                float v = acc[i][j] + bias[col];
                if (ACT == 1) v = v / (1.f + expf(-v));  // silu
                *cp = v;
            }
        }
    }
}

// ---------------- launch ----------------
extern "C" void kernel_launch(void* const* d_in, const int* in_sizes, int n_in,
                              void* d_out, int out_size) {
    const float* x    = (const float*)d_in[0];
    const int*   batch= (const int*)d_in[1];
    const int*   ntm  = (const int*)d_in[2];
    const float* aw1  = (const float*)d_in[4];
    const float* ab1  = (const float*)d_in[5];
    const float* aw2  = (const float*)d_in[6];
    const float* ab2  = (const float*)d_in[7];
    const float* we   = (const float*)d_in[8];
    const float* be   = (const float*)d_in[9];
    const float* wv   = (const float*)d_in[10];
    const float* bv   = (const float*)d_in[11];
    const float* wp   = (const float*)d_in[12];
    const float* bp   = (const float*)d_in[13];
    const float* w1   = (const float*)d_in[14];
    const float* b1   = (const float*)d_in[15];
    const float* w2   = (const float*)d_in[16];
    const float* b2   = (const float*)d_in[17];
    float* out = (float*)d_out;

    void *p_ts, *p_comb, *p_H, *p_wcat;
    cudaGetSymbolAddress(&p_ts,   g_typesums);
    cudaGetSymbolAddress(&p_comb, g_combined);
    cudaGetSymbolAddress(&p_H,    g_H);
    cudaGetSymbolAddress(&p_wcat, g_wcat);
    float* ts   = (float*)p_ts;
    float* comb = (float*)p_comb;
    float* Hbuf = (float*)p_H;
    float* wcat = (float*)p_wcat;

    cudaFuncSetAttribute(k1_mma, cudaFuncAttributeMaxDynamicSharedMemorySize, K1_SMEM);

    k0_bounds<<<(NN + 255) / 256, 256>>>(batch, ntm);
    k_wprep<<<(DD * HH + 255) / 256, 256>>>(aw1);
    k1_mma<<<148, 256, K1_SMEM>>>(x, ab1, aw2, ab2);
    k2a_stats<<<BB, 128>>>();
    k2b_pool<<<BB, 512>>>(x, be, bv, bp);
    k_cat<<<768, 256>>>(we, wv, wp);

    // phys_pool: combined[:,512:768] += typesums @ wcat
    gemm_k<0><<<dim3(256 / 64, BB / 64), 256>>>(ts, 768, wcat, 256,
                                                comb, 768, 512, nullptr, 768);
    // H = silu(combined @ w1 + b1)
    gemm_k<1><<<dim3(512 / 64, BB / 64), 256>>>(comb, 768, w1, 512,
                                                Hbuf, 512, 0, b1, 768);
    // out = H @ w2 + b2
    gemm_k<2><<<dim3(256 / 64, BB / 64), 256>>>(Hbuf, 512, w2, 256,
                                                out, 256, 0, b2, 512);
}

// round 9
// speedup vs baseline: 2.1420x; 1.1256x over previous
#include <cuda_runtime.h>
#include <cuda_bf16.h>
#include <math.h>
#include <stdint.h>

// Problem constants (fixed shapes)
#define NN 200000
#define DD 256
#define HH 128      // D/2
#define BB 1024
#define OUTD 256
#define NTILES ((NN + 127) / 128)   // 1563

// ---------------- scratch (device globals, no allocation) ----------------
__device__ int   g_segstart[BB + 1];
__device__ float g_s[NN];                 // per-node attention score
__device__ uint8_t g_t8[NN];              // per-node type 0/1/2
__device__ float g_m[BB];                 // segment max of s
__device__ float g_iz[BB];                // 1 / segment sum exp
__device__ float g_cnt[BB * 4];           // c0, c1, c2, 1/count
__device__ float g_typesums[BB * 768];    // [B][3][256]
__device__ float g_combined[BB * 768];    // [mean | attn | phys]
__device__ float g_H[BB * 512];           // hidden of final MLP
__device__ float g_wcat[768 * 256];       // [we; wv; wp]
__device__ uint32_t g_wT[HH * DD];        // aw1^T as tf32 bits [j][k]

__device__ __forceinline__ uint32_t smem_u32(const void* p) {
    uint32_t a;
    asm("{ .reg .u64 t; cvta.to.shared.u64 t, %1; cvt.u32.u64 %0, t; }"
        : "=r"(a) : "l"(p));
    return a;
}

// ---------------- K0: segment boundaries + packed node type
__global__ void k0_bounds(const int* __restrict__ batch,
                          const int* __restrict__ ntm) {
    int i = blockIdx.x * 256 + threadIdx.x;
    if (i < NN) {
        if (i == 0 || batch[i] != batch[i - 1]) g_segstart[batch[i]] = i;
        g_t8[i] = (uint8_t)(ntm[i * 3 + 1] + 2 * ntm[i * 3 + 2]);
    }
    if (i == 0) g_segstart[BB] = NN;
}

// ---------------- weight prep: aw1 [k][j] fp32 -> transposed tf32 [j][k]
__global__ void k_wprep(const float* __restrict__ aw1) {
    int t = blockIdx.x * 256 + threadIdx.x;
    if (t < DD * HH) {
        int k = t >> 7;
        int j = t & 127;
        uint32_t u;
        asm("cvt.rna.tf32.f32 %0, %1;" : "=r"(u) : "f"(aw1[t]));
        g_wT[j * DD + k] = u;
    }
}

// ============ K1: scores via mma.sync m16n8k8 TF32 ============
// Per tile (128 nodes): D[128n][128j] = X_tf32 @ W_tf32^T over K=256
// Then s = tanh(D + ab1) @ aw2 + ab2.
//
// smem (dynamic, 1024-aligned base):
//   [0]      aw2s float[128]
//   [512]    ab1s float[128]
//   [1024]   red  float[256]
//   [2048]   W    128 rows x 1024B (tf32, swizzled)   = 128 KB
//   [133120] X    128 rows x 256B (kc chunk, swz)     =  32 KB
#define K1_AW2S 0
#define K1_AB1S 512
#define K1_RED  1024
#define K1_W    2048
#define K1_X    (K1_W + 131072)
#define K1_SMEM (K1_X + 32768 + 1024)

#define LDSM_X4(r0, r1, r2, r3, a) \
    asm volatile("ldmatrix.sync.aligned.m8n8.x4.shared.b16 {%0,%1,%2,%3}, [%4];" \
                 : "=r"(r0), "=r"(r1), "=r"(r2), "=r"(r3) : "r"(a))
#define LDSM_X2(r0, r1, a) \
    asm volatile("ldmatrix.sync.aligned.m8n8.x2.shared.b16 {%0,%1}, [%2];" \
                 : "=r"(r0), "=r"(r1) : "r"(a))
#define MMATF32(d, a, b) \
    asm volatile("mma.sync.aligned.m16n8k8.row.col.f32.tf32.tf32.f32 " \
                 "{%0,%1,%2,%3}, {%4,%5,%6,%7}, {%8,%9}, {%0,%1,%2,%3};" \
                 : "+f"((d)[0]), "+f"((d)[1]), "+f"((d)[2]), "+f"((d)[3]) \
                 : "r"((a)[0]), "r"((a)[1]), "r"((a)[2]), "r"((a)[3]), \
                   "r"((b)[0]), "r"((b)[1]))

__global__ __launch_bounds__(256, 1)
void k1_mma(const float* __restrict__ x,
            const float* __restrict__ ab1,
            const float* __restrict__ aw2,
            const float* __restrict__ ab2) {
    extern __shared__ char raw[];
    char* alig = (char*)((((uintptr_t)raw) + 1023) & ~(uintptr_t)1023);
    const uint32_t sb = smem_u32(alig);

    const int tid  = threadIdx.x;
    const int w    = tid >> 5;
    const int lane = tid & 31;
    const int wm   = (w & 3) * 32;      // row base of this warp
    const int jb   = (w >> 2) * 64;     // col base of this warp

    float* aw2s = (float*)(alig + K1_AW2S);
    float* ab1s = (float*)(alig + K1_AB1S);
    float* red  = (float*)(alig + K1_RED);

    if (tid < 128) {
        aw2s[tid] = aw2[tid];
        ab1s[tid] = ab1[tid];
    }
    const float ab2v = ab2[0];

    // ---- weights -> smem once (tf32, rows of 1024B, swizzled 16B units) ----
    for (int f = tid; f < 8192; f += 256) {          // 8192 uint4 = 128K
        int j = f >> 6;                               // 0..127
        int u = f & 63;                               // 16B unit within row
        uint4 v = *(const uint4*)(g_wT + j * DD + u * 4);
        uint32_t dst = (uint32_t)(K1_W + j * 1024 + ((u * 16) ^ ((j & 7) << 4)));
        *(uint4*)(alig + dst) = v;
    }
    __syncthreads();

    // ldmatrix lane-address components (constant per thread)
    const int arow_off = lane & 15;
    const int akoff    = (lane >> 4) << 4;   // +16B for k 4..7
    const int brow_off = lane & 7;
    const int bkoff    = (lane & 8) << 1;    // +16B for k 4..7

    for (int t = blockIdx.x; t < NTILES; t += gridDim.x) {
        const int base = t * 128;

        float acc[2][8][4];
#pragma unroll
        for (int mi = 0; mi < 2; mi++)
#pragma unroll
            for (int ni = 0; ni < 8; ni++)
#pragma unroll
                for (int q = 0; q < 4; q++) acc[mi][ni][q] = 0.f;

        // register prefetch: 8 float4/thread = one 128x64 chunk
        float4 pv[8];
        {
#pragma unroll
            for (int r = 0; r < 8; r++) {
                int f = tid + 256 * r;
                int row = f >> 4, q = f & 15;
                int node = base + row;
                pv[r] = (node < NN)
                    ? *(const float4*)(x + (size_t)node * DD + q * 4)
                    : make_float4(0.f, 0.f, 0.f, 0.f);
            }
        }

        for (int kc = 0; kc < 4; kc++) {
            // ---- convert prefetched chunk to tf32 in smem (swizzled) ----
#pragma unroll
            for (int r = 0; r < 8; r++) {
                int f = tid + 256 * r;
                int row = f >> 4, q = f & 15;
                float4 v = pv[r];
                uint4 tv;
                asm("cvt.rna.tf32.f32 %0, %1;" : "=r"(tv.x) : "f"(v.x));
                asm("cvt.rna.tf32.f32 %0, %1;" : "=r"(tv.y) : "f"(v.y));
                asm("cvt.rna.tf32.f32 %0, %1;" : "=r"(tv.z) : "f"(v.z));
                asm("cvt.rna.tf32.f32 %0, %1;" : "=r"(tv.w) : "f"(v.w));
                uint32_t s0 = (uint32_t)(K1_X + row * 256 +
                                         ((q * 16) ^ ((row & 7) << 4)));
                *(uint4*)(alig + s0) = tv;
            }
            __syncthreads();

            // ---- prefetch next chunk while MMAs run ----
            if (kc < 3) {
                const int kc64 = (kc + 1) * 64;
#pragma unroll
                for (int r = 0; r < 8; r++) {
                    int f = tid + 256 * r;
                    int row = f >> 4, q = f & 15;
                    int node = base + row;
                    pv[r] = (node < NN)
                        ? *(const float4*)(x + (size_t)node * DD + kc64 + q * 4)
                        : make_float4(0.f, 0.f, 0.f, 0.f);
                }
            }

            // ---- MMA over this 64-wide K chunk (8 k8 steps) ----
#pragma unroll
            for (int ks = 0; ks < 8; ks++) {
                const int kbX = ks * 32;                 // bytes in X row
                const int wkb = kc * 256 + ks * 32;      // bytes in W row

                uint32_t a[2][4];
#pragma unroll
                for (int mi = 0; mi < 2; mi++) {
                    int row = wm + mi * 16 + arow_off;
                    uint32_t ao = (uint32_t)(K1_X + row * 256 +
                        ((kbX + akoff) ^ ((row & 7) << 4)));
                    LDSM_X4(a[mi][0], a[mi][1], a[mi][2], a[mi][3], sb + ao);
                }
                uint32_t b[8][2];
#pragma unroll
                for (int ni = 0; ni < 8; ni++) {
                    int jrow = jb + ni * 8 + brow_off;
                    uint32_t bo = (uint32_t)(K1_W + jrow * 1024 +
                        ((wkb + bkoff) ^ ((jrow & 7) << 4)));
                    LDSM_X2(b[ni][0], b[ni][1], sb + bo);
                }
#pragma unroll
                for (int mi = 0; mi < 2; mi++)
#pragma unroll
                    for (int ni = 0; ni < 8; ni++)
                        MMATF32(acc[mi][ni], a[mi], b[ni]);
            }
            __syncthreads();
        }

        // ---- epilogue: s = tanh(acc + ab1) @ aw2, reduce, write ----
#pragma unroll
        for (int mi = 0; mi < 2; mi++) {
            float plo = 0.f, phi = 0.f;
#pragma unroll
            for (int ni = 0; ni < 8; ni++) {
                int c0 = jb + ni * 8 + (lane & 3) * 2;
                float w0 = aw2s[c0], w1 = aw2s[c0 + 1];
                float b0 = ab1s[c0], b1 = ab1s[c0 + 1];
                plo += tanhf(acc[mi][ni][0] + b0) * w0
                     + tanhf(acc[mi][ni][1] + b1) * w1;
                phi += tanhf(acc[mi][ni][2] + b0) * w0
                     + tanhf(acc[mi][ni][3] + b1) * w1;
            }
            plo += __shfl_xor_sync(0xFFFFFFFFu, plo, 1);
            plo += __shfl_xor_sync(0xFFFFFFFFu, plo, 2);
            phi += __shfl_xor_sync(0xFFFFFFFFu, phi, 1);
            phi += __shfl_xor_sync(0xFFFFFFFFu, phi, 2);
            if ((lane & 3) == 0) {
                int rlo = wm + mi * 16 + (lane >> 2);
                red[(w >> 2) * 128 + rlo]     = plo;
                red[(w >> 2) * 128 + rlo + 8] = phi;
            }
        }
        __syncthreads();
        if (tid < 128) {
            int node = base + tid;
            if (node < NN) g_s[node] = red[tid] + red[128 + tid] + ab2v;
        }
        __syncthreads();
    }
}

// ---------------- K2a: per-segment stats (m, 1/z, type counts, 1/count)
__global__ __launch_bounds__(128)
void k2a_stats() {
    const int b = blockIdx.x;
    const int tid = threadIdx.x;
    const int st = g_segstart[b];
    const int en = g_segstart[b + 1];

    __shared__ float red[128];
    __shared__ int   redi[128];

    float m = -1e30f;
    int cp = 0;                               // c0 | c1<<10 | c2<<20
    for (int i = st + tid; i < en; i += 128) {
        m = fmaxf(m, g_s[i]);
        int t = g_t8[i];
        cp += 1 << (t * 10);
    }
    red[tid] = m; redi[tid] = cp; __syncthreads();
    for (int off = 64; off > 0; off >>= 1) {
        if (tid < off) {
            red[tid] = fmaxf(red[tid], red[tid + off]);
            redi[tid] += redi[tid + off];
        }
        __syncthreads();
    }
    m = red[0]; cp = redi[0]; __syncthreads();

    float z = 0.f;
    for (int i = st + tid; i < en; i += 128) z += expf(g_s[i] - m);
    red[tid] = z; __syncthreads();
    for (int off = 64; off > 0; off >>= 1) {
        if (tid < off) red[tid] += red[tid + off];
        __syncthreads();
    }
    if (tid == 0) {
        g_m[b]  = m;
        g_iz[b] = 1.f / red[0];
        g_cnt[b * 4 + 0] = (float)(cp & 1023);
        g_cnt[b * 4 + 1] = (float)((cp >> 10) & 1023);
        g_cnt[b * 4 + 2] = (float)((cp >> 20) & 1023);
        g_cnt[b * 4 + 3] = 1.f / (float)(en - st);
    }
}

// ---------------- K2b: pools. 512 thr = 4 i-groups x 128 column-threads.
__global__ __launch_bounds__(512)
void k2b_pool(const float* __restrict__ x,
              const float* __restrict__ be,
              const float* __restrict__ bv,
              const float* __restrict__ bp) {
    const int b   = blockIdx.x;
    const int tid = threadIdx.x;
    const int g   = tid >> 7;        // i-group 0..3
    const int col = tid & 127;       // column pair index
    const int d0  = col * 2;
    const int st  = g_segstart[b];
    const int en  = g_segstart[b + 1];
    const float m  = g_m[b];
    const float iz = g_iz[b];

    __shared__ float sred[512 * 10];  // 20 KB

    float a0 = 0.f, a1 = 0.f, w0 = 0.f, w1 = 0.f;
    float t00 = 0.f, t01 = 0.f, t10 = 0.f, t11 = 0.f, t20 = 0.f, t21 = 0.f;

    const float* xp = x + d0;

    int i = st + g;
    // unrolled by 2 (group stride 4)
    for (; i + 4 < en; i += 8) {
        float  s0 = g_s[i],      s1 = g_s[i + 4];
        int    ty0 = g_t8[i],    ty1 = g_t8[i + 4];
        float2 v0 = *(const float2*)(xp + (size_t)i * DD);
        float2 v1 = *(const float2*)(xp + (size_t)(i + 4) * DD);
        float  e0 = expf(s0 - m) * iz;
        float  e1 = expf(s1 - m) * iz;

        a0 += v0.x + v1.x;  a1 += v0.y + v1.y;
        w0 = fmaf(e0, v0.x, w0); w0 = fmaf(e1, v1.x, w0);
        w1 = fmaf(e0, v0.y, w1); w1 = fmaf(e1, v1.y, w1);

        float m00 = (ty0 == 0), m01 = (ty0 == 1), m02 = (ty0 == 2);
        float m10 = (ty1 == 0), m11 = (ty1 == 1), m12 = (ty1 == 2);
        t00 = fmaf(m00, v0.x, t00); t00 = fmaf(m10, v1.x, t00);
        t01 = fmaf(m00, v0.y, t01); t01 = fmaf(m10, v1.y, t01);
        t10 = fmaf(m01, v0.x, t10); t10 = fmaf(m11, v1.x, t10);
        t11 = fmaf(m01, v0.y, t11); t11 = fmaf(m11, v1.y, t11);
        t20 = fmaf(m02, v0.x, t20); t20 = fmaf(m12, v1.x, t20);
        t21 = fmaf(m02, v0.y, t21); t21 = fmaf(m12, v1.y, t21);
    }
    for (; i < en; i += 4) {
        float  s0 = g_s[i];
        int    ty0 = g_t8[i];
        float2 v0 = *(const float2*)(xp + (size_t)i * DD);
        float  e0 = expf(s0 - m) * iz;
        a0 += v0.x; a1 += v0.y;
        w0 = fmaf(e0, v0.x, w0); w1 = fmaf(e0, v0.y, w1);
        float m00 = (ty0 == 0), m01 = (ty0 == 1), m02 = (ty0 == 2);
        t00 = fmaf(m00, v0.x, t00); t01 = fmaf(m00, v0.y, t01);
        t10 = fmaf(m01, v0.x, t10); t11 = fmaf(m01, v0.y, t11);
        t20 = fmaf(m02, v0.x, t20); t21 = fmaf(m02, v0.y, t21);
    }

    float* sp = sred + tid * 10;
    sp[0] = a0;  sp[1] = a1;  sp[2] = w0;  sp[3] = w1;
    sp[4] = t00; sp[5] = t01; sp[6] = t10; sp[7] = t11;
    sp[8] = t20; sp[9] = t21;
    __syncthreads();

    if (tid < 128) {
        float r[10];
#pragma unroll
        for (int q = 0; q < 10; q++) r[q] = sred[tid * 10 + q];
#pragma unroll
        for (int gg = 1; gg < 4; gg++)
#pragma unroll
            for (int q = 0; q < 10; q++) r[q] += sred[(gg * 128 + tid) * 10 + q];

        float f0   = g_cnt[b * 4 + 0];
        float f1   = g_cnt[b * 4 + 1];
        float f2   = g_cnt[b * 4 + 2];
        float invc = g_cnt[b * 4 + 3];

        float* comb = g_combined + (size_t)b * 768;
        comb[d0]           = r[0] * invc;  comb[d0 + 1]       = r[1] * invc;
        comb[256 + d0]     = r[2];         comb[256 + d0 + 1] = r[3];

        float* ts = g_typesums + (size_t)b * 768;
        ts[d0]           = r[4]; ts[d0 + 1]       = r[5];
        ts[256 + d0]     = r[6]; ts[256 + d0 + 1] = r[7];
        ts[512 + d0]     = r[8]; ts[512 + d0 + 1] = r[9];

        comb[512 + d0]     = f0 * be[d0]     + f1 * bv[d0]     + f2 * bp[d0];
        comb[512 + d0 + 1] = f0 * be[d0 + 1] + f1 * bv[d0 + 1] + f2 * bp[d0 + 1];
    }
}

// ---------------- weight concat [we; wv; wp] -> g_wcat[768][256]
__global__ void k_cat(const float* __restrict__ we,
                      const float* __restrict__ wv,
                      const float* __restrict__ wp) {
    int t = blockIdx.x * 256 + threadIdx.x;
    if (t < 768 * 256) {
        int k = t >> 8;
        int n = t & 255;
        float v;
        if (k < 256)      v = we[k * 256 + n];
        else if (k < 512) v = wv[(k - 256) * 256 + n];
        else              v = wp[(k - 512) * 256 + n];
        g_wcat[t] = v;
    }
}

// ---------------- generic tiled GEMM: C = act(A[M][K] @ W[K][N] + bias)
template <int ACT>
__global__ __launch_bounds__(256)
void gemm_k(const float* __restrict__ A, int lda,
            const float* __restrict__ W, int ldw,
            float* __restrict__ C, int ldc, int coff,
            const float* __restrict__ bias, int Kdim) {
    __shared__ float As[32][64];
    __shared__ float Ws[32][64];

    const int tid = threadIdx.x;
    const int tx = tid & 15;
    const int ty = tid >> 4;
    const int colb = blockIdx.x * 64;
    const int rowb = blockIdx.y * 64;

    float acc[4][4];
#pragma unroll
    for (int i = 0; i < 4; i++)
#pragma unroll
        for (int j = 0; j < 4; j++) acc[i][j] = 0.f;

    for (int kb = 0; kb < Kdim; kb += 32) {
        __syncthreads();
#pragma unroll
        for (int r = 0; r < 2; r++) {
            int flat = tid + 256 * r;
            int row = flat >> 3;
            int q = flat & 7;
            float4 v = *(const float4*)(A + (size_t)(rowb + row) * lda + kb + 4 * q);
            As[4 * q + 0][row] = v.x; As[4 * q + 1][row] = v.y;
            As[4 * q + 2][row] = v.z; As[4 * q + 3][row] = v.w;
        }
#pragma unroll
        for (int r = 0; r < 2; r++) {
            int flat = tid + 256 * r;
            int kk = flat >> 4;
            int jq = flat & 15;
            float4 v = *(const float4*)(W + (size_t)(kb + kk) * ldw + colb + 4 * jq);
            *(float4*)&Ws[kk][4 * jq] = v;
        }
        __syncthreads();

#pragma unroll 8
        for (int kk = 0; kk < 32; kk++) {
            float4 av = *(const float4*)&As[kk][4 * ty];
            float4 wv = *(const float4*)&Ws[kk][4 * tx];
            float a[4] = {av.x, av.y, av.z, av.w};
            float wr[4] = {wv.x, wv.y, wv.z, wv.w};
#pragma unroll
            for (int i = 0; i < 4; i++)
#pragma unroll
                for (int j = 0; j < 4; j++) acc[i][j] += a[i] * wr[j];
        }
    }

#pragma unroll
    for (int i = 0; i < 4; i++) {
        int row = rowb + 4 * ty + i;
#pragma unroll
        for (int j = 0; j < 4; j++) {
            int col = colb + 4 * tx + j;
            float* cp = C + (size_t)row * ldc + coff + col;
            if (ACT == 0) {
                *cp += acc[i][j];
            } else {
                float v = acc[i][j] + bias[col];
                if (ACT == 1) v = v / (1.f + expf(-v));  // silu
                *cp = v;
            }
        }
    }
}

// ---------------- launch ----------------
extern "C" void kernel_launch(void* const* d_in, const int* in_sizes, int n_in,
                              void* d_out, int out_size) {
    const float* x    = (const float*)d_in[0];
    const int*   batch= (const int*)d_in[1];
    const int*   ntm  = (const int*)d_in[2];
    const float* aw1  = (const float*)d_in[4];
    const float* ab1  = (const float*)d_in[5];
    const float* aw2  = (const float*)d_in[6];
    const float* ab2  = (const float*)d_in[7];
    const float* we   = (const float*)d_in[8];
    const float* be   = (const float*)d_in[9];
    const float* wv   = (const float*)d_in[10];
    const float* bv   = (const float*)d_in[11];
    const float* wp   = (const float*)d_in[12];
    const float* bp   = (const float*)d_in[13];
    const float* w1   = (const float*)d_in[14];
    const float* b1   = (const float*)d_in[15];
    const float* w2   = (const float*)d_in[16];
    const float* b2   = (const float*)d_in[17];
    float* out = (float*)d_out;

    void *p_ts, *p_comb, *p_H, *p_wcat;
    cudaGetSymbolAddress(&p_ts,   g_typesums);
    cudaGetSymbolAddress(&p_comb, g_combined);
    cudaGetSymbolAddress(&p_H,    g_H);
    cudaGetSymbolAddress(&p_wcat, g_wcat);
    float* ts   = (float*)p_ts;
    float* comb = (float*)p_comb;
    float* Hbuf = (float*)p_H;
    float* wcat = (float*)p_wcat;

    cudaFuncSetAttribute(k1_mma, cudaFuncAttributeMaxDynamicSharedMemorySize, K1_SMEM);

    k0_bounds<<<(NN + 255) / 256, 256>>>(batch, ntm);
    k_wprep<<<(DD * HH + 255) / 256, 256>>>(aw1);
    k1_mma<<<148, 256, K1_SMEM>>>(x, ab1, aw2, ab2);
    k2a_stats<<<BB, 128>>>();
    k2b_pool<<<BB, 512>>>(x, be, bv, bp);
    k_cat<<<768, 256>>>(we, wv, wp);

    // phys_pool: combined[:,512:768] += typesums @ wcat
    gemm_k<0><<<dim3(256 / 64, BB / 64), 256>>>(ts, 768, wcat, 256,
                                                comb, 768, 512, nullptr, 768);
    // H = silu(combined @ w1 + b1)
    gemm_k<1><<<dim3(512 / 64, BB / 64), 256>>>(comb, 768, w1, 512,
                                                Hbuf, 512, 0, b1, 768);
    // out = H @ w2 + b2
    gemm_k<2><<<dim3(256 / 64, BB / 64), 256>>>(Hbuf, 512, w2, 256,
                                                out, 256, 0, b2, 512);
}